// round 4
// baseline (speedup 1.0000x reference)
#include <cuda_runtime.h>

#define N_MENTIONS 65536
#define D 256
#define LANES 64              // threads per mention group (64 x float4 = 256 floats)
#define GROUPS_PER_BLOCK 4    // 256 threads per block
#define BATCH 8               // gathers in flight per thread

// Scratch: CSR row pointers built each launch (allocation-free requirement).
__device__ int g_row_ptr[N_MENTIONS + 1];

// Prologue: boundary-fill row_ptr from sorted COO rows, int4-vectorized.
__global__ void build_rowptr_kernel(const int4* __restrict__ spm_rows4, int nnz)
{
    int t = blockIdx.x * blockDim.x + threadIdx.x;
    int j0 = t * 4;
    if (j0 >= nnz) return;

    const int4 r4 = __ldg(spm_rows4 + t);
    int rp;
    if (j0 == 0) rp = -1;
    else         rp = __ldg(((const int*)spm_rows4) + j0 - 1);

    int rr[4] = {r4.x, r4.y, r4.z, r4.w};
    #pragma unroll
    for (int k = 0; k < 4; ++k) {
        const int r = rr[k];
        for (int row = rp + 1; row <= r; ++row) g_row_ptr[row] = j0 + k;
        rp = r;
    }
    if (j0 + 4 >= nnz) {
        for (int row = rp + 1; row <= N_MENTIONS; ++row) g_row_ptr[row] = nnz;
    }
}

// Two-phase batched gather: load BATCH codes/vals (independent, mostly L2 hits),
// then issue BATCH independent 16B gathers back-to-back for deep MLP, then FMA.
// Out-of-range slots clamp to end-1 (same row as a real gather -> L1/L2 hit)
// with val=0, so they cost no DRAM traffic and no branches.
__global__ __launch_bounds__(LANES * GROUPS_PER_BLOCK, 4)
void mention_segsum_kernel(const float4* __restrict__ token_ft,   // [N_TOKENS, 64] float4
                           const int*    __restrict__ token_code, // [NNZ]
                           const float*  __restrict__ spm_vals,   // [NNZ]
                           float4*       __restrict__ out)        // [N_MENTIONS, 64] float4
{
    const int group = blockIdx.x * GROUPS_PER_BLOCK + (threadIdx.x / LANES);
    const int lane  = threadIdx.x & (LANES - 1);
    if (group >= N_MENTIONS) return;

    const int start = g_row_ptr[group];
    const int end   = g_row_ptr[group + 1];

    float4 acc = make_float4(0.f, 0.f, 0.f, 0.f);

    if (start < end) {
        for (int base = start; base < end; base += BATCH) {
            int   c[BATCH];
            float v[BATCH];
            #pragma unroll
            for (int k = 0; k < BATCH; ++k) {
                const int  jj  = base + k;
                const bool p   = jj < end;
                const int  idx = p ? jj : (end - 1);
                c[k] = __ldg(token_code + idx);
                v[k] = p ? __ldg(spm_vals + idx) : 0.f;
            }
            float4 f[BATCH];
            #pragma unroll
            for (int k = 0; k < BATCH; ++k)
                f[k] = __ldcg(token_ft + (size_t)c[k] * (D / 4) + lane);
            #pragma unroll
            for (int k = 0; k < BATCH; ++k) {
                acc.x += v[k] * f[k].x;
                acc.y += v[k] * f[k].y;
                acc.z += v[k] * f[k].z;
                acc.w += v[k] * f[k].w;
            }
        }
    }

    // One coalesced 1KB streaming store per mention row; empty segments write zeros.
    __stcs(out + (size_t)group * (D / 4) + lane, acc);
}

extern "C" void kernel_launch(void* const* d_in, const int* in_sizes, int n_in,
                              void* d_out, int out_size)
{
    const float* token_ft   = (const float*)d_in[0]; // [262144, 256] f32
    const int*   token_code = (const int*)  d_in[1]; // [524288] i32
    const int*   spm_rows   = (const int*)  d_in[2]; // [524288] i32 sorted
    const float* spm_vals   = (const float*)d_in[3]; // [524288] f32
    float*       out        = (float*)d_out;         // [65536, 256] f32

    const int nnz = in_sizes[1];

    const int pro_threads = 256;
    const int pro_work    = (nnz + 3) / 4;
    build_rowptr_kernel<<<(pro_work + pro_threads - 1) / pro_threads, pro_threads>>>(
        (const int4*)spm_rows, nnz);

    const int threads = LANES * GROUPS_PER_BLOCK;                                 // 256
    const int blocks  = (N_MENTIONS + GROUPS_PER_BLOCK - 1) / GROUPS_PER_BLOCK;   // 16384

    mention_segsum_kernel<<<blocks, threads>>>(
        (const float4*)token_ft, token_code, spm_vals, (float4*)out);
}

// round 5
// speedup vs baseline: 1.0435x; 1.0435x over previous
#include <cuda_runtime.h>

#define N_MENTIONS 65536
#define D 256
#define LANES 64              // threads per group (64 x float4 = one 256-float row)
#define GROUPS_PER_BLOCK 4    // 256 threads per block
#define ROWS_PER_GROUP 4      // consecutive mention rows per group (contiguous nnz run)

// Scratch: CSR row pointers built each launch (allocation-free requirement).
__device__ int g_row_ptr[N_MENTIONS + 1];

// Prologue: boundary-fill row_ptr from sorted COO rows, int4-vectorized.
__global__ void build_rowptr_kernel(const int4* __restrict__ spm_rows4, int nnz)
{
    int t = blockIdx.x * blockDim.x + threadIdx.x;
    int j0 = t * 4;
    if (j0 >= nnz) return;

    const int4 r4 = __ldg(spm_rows4 + t);
    int rp;
    if (j0 == 0) rp = -1;
    else         rp = __ldg(((const int*)spm_rows4) + j0 - 1);

    int rr[4] = {r4.x, r4.y, r4.z, r4.w};
    #pragma unroll
    for (int k = 0; k < 4; ++k) {
        const int r = rr[k];
        for (int row = rp + 1; row <= r; ++row) g_row_ptr[row] = j0 + k;
        rp = r;
    }
    if (j0 + 4 >= nnz) {
        for (int row = rp + 1; row <= N_MENTIONS; ++row) g_row_ptr[row] = nnz;
    }
}

// Each 64-thread group owns ROWS_PER_GROUP consecutive mention rows, whose nnz
// form ONE contiguous run (~32 elems). The group streams that run densely in
// 4-wide gather batches — the LSU pipeline stays full across row boundaries —
// and flushes the accumulator at (warp-uniform) row transitions.
__global__ __launch_bounds__(LANES * GROUPS_PER_BLOCK)
void mention_segsum_kernel(const float4* __restrict__ token_ft,   // [N_TOKENS, 64] float4
                           const int*    __restrict__ token_code, // [NNZ]
                           const float*  __restrict__ spm_vals,   // [NNZ]
                           float4*       __restrict__ out)        // [N_MENTIONS, 64] float4
{
    const int group = blockIdx.x * GROUPS_PER_BLOCK + (threadIdx.x / LANES);
    const int lane  = threadIdx.x & (LANES - 1);
    const int r0    = group * ROWS_PER_GROUP;
    if (r0 >= N_MENTIONS) return;

    int p[ROWS_PER_GROUP + 1];
    #pragma unroll
    for (int i = 0; i <= ROWS_PER_GROUP; ++i) p[i] = g_row_ptr[r0 + i];
    const int start = p[0];
    const int end   = p[ROWS_PER_GROUP];

    float4 acc = make_float4(0.f, 0.f, 0.f, 0.f);
    int cur = 0;   // row (within group) currently being accumulated

    for (int base = start; base < end; base += 4) {
        int   c[4];
        float v[4];
        #pragma unroll
        for (int k = 0; k < 4; ++k) {
            const int  jj  = base + k;
            const bool ok  = jj < end;
            const int  idx = ok ? jj : (end - 1);   // clamp: duplicate row -> L2 hit
            c[k] = __ldg(token_code + idx);
            v[k] = ok ? __ldg(spm_vals + idx) : 0.f;
        }
        float4 f[4];
        #pragma unroll
        for (int k = 0; k < 4; ++k)
            f[k] = __ldcg(token_ft + (size_t)c[k] * (D / 4) + lane);

        #pragma unroll
        for (int k = 0; k < 4; ++k) {
            const int jj = base + k;
            if (jj < end) {
                // Warp-uniform row-boundary flush (handles empty rows too).
                while (cur < ROWS_PER_GROUP - 1 && jj >= p[cur + 1]) {
                    __stcs(out + (size_t)(r0 + cur) * (D / 4) + lane, acc);
                    acc = make_float4(0.f, 0.f, 0.f, 0.f);
                    ++cur;
                }
                acc.x += v[k] * f[k].x;
                acc.y += v[k] * f[k].y;
                acc.z += v[k] * f[k].z;
                acc.w += v[k] * f[k].w;
            }
        }
    }

    // Final flush: current row gets acc, remaining rows (possibly all, if the
    // whole run was empty) get zeros.
    __stcs(out + (size_t)(r0 + cur) * (D / 4) + lane, acc);
    const float4 zero = make_float4(0.f, 0.f, 0.f, 0.f);
    for (int m = cur + 1; m < ROWS_PER_GROUP; ++m)
        __stcs(out + (size_t)(r0 + m) * (D / 4) + lane, zero);
}

extern "C" void kernel_launch(void* const* d_in, const int* in_sizes, int n_in,
                              void* d_out, int out_size)
{
    const float* token_ft   = (const float*)d_in[0]; // [262144, 256] f32
    const int*   token_code = (const int*)  d_in[1]; // [524288] i32
    const int*   spm_rows   = (const int*)  d_in[2]; // [524288] i32 sorted
    const float* spm_vals   = (const float*)d_in[3]; // [524288] f32
    float*       out        = (float*)d_out;         // [65536, 256] f32

    const int nnz = in_sizes[1];

    const int pro_threads = 256;
    const int pro_work    = (nnz + 3) / 4;
    build_rowptr_kernel<<<(pro_work + pro_threads - 1) / pro_threads, pro_threads>>>(
        (const int4*)spm_rows, nnz);

    const int groups  = N_MENTIONS / ROWS_PER_GROUP;                   // 16384
    const int threads = LANES * GROUPS_PER_BLOCK;                      // 256
    const int blocks  = (groups + GROUPS_PER_BLOCK - 1) / GROUPS_PER_BLOCK; // 4096

    mention_segsum_kernel<<<blocks, threads>>>(
        (const float4*)token_ft, token_code, spm_vals, (float4*)out);
}

// round 6
// speedup vs baseline: 1.0465x; 1.0028x over previous
#include <cuda_runtime.h>

#define N_MENTIONS 65536
#define D 256
#define LANES 64              // threads per mention group (64 x float4 = 256 floats)
#define GROUPS_PER_BLOCK 8    // 512 threads per block

// Scratch: CSR row pointers built each launch (allocation-free requirement).
__device__ int g_row_ptr[N_MENTIONS + 1];

// Prologue: boundary-fill row_ptr from sorted COO rows, int4-vectorized.
__global__ __launch_bounds__(512)
void build_rowptr_kernel(const int4* __restrict__ spm_rows4, int nnz)
{
    int t = blockIdx.x * blockDim.x + threadIdx.x;
    int j0 = t * 4;
    if (j0 >= nnz) return;

    const int4 r4 = __ldg(spm_rows4 + t);
    int rp;
    if (j0 == 0) rp = -1;
    else         rp = __ldg(((const int*)spm_rows4) + j0 - 1);

    int rr[4] = {r4.x, r4.y, r4.z, r4.w};
    #pragma unroll
    for (int k = 0; k < 4; ++k) {
        const int r = rr[k];
        for (int row = rp + 1; row <= r; ++row) g_row_ptr[row] = j0 + k;
        rp = r;
    }
    if (j0 + 4 >= nnz) {
        for (int row = rp + 1; row <= N_MENTIONS; ++row) g_row_ptr[row] = nnz;
    }
}

__global__ __launch_bounds__(LANES * GROUPS_PER_BLOCK)
void mention_segsum_kernel(const float4* __restrict__ token_ft,   // [N_TOKENS, 64] float4
                           const int*    __restrict__ token_code, // [NNZ]
                           const float*  __restrict__ spm_vals,   // [NNZ]
                           float4*       __restrict__ out)        // [N_MENTIONS, 64] float4
{
    const int group = blockIdx.x * GROUPS_PER_BLOCK + (threadIdx.x / LANES);
    const int lane  = threadIdx.x & (LANES - 1);

    const int start = __ldg(g_row_ptr + group);
    const int end   = __ldg(g_row_ptr + group + 1);

    float4 acc = make_float4(0.f, 0.f, 0.f, 0.f);

    // 4-wide dense mainloop: 4 independent 1KB row gathers in flight per warp.
    // __ldcg: L2-only — gathered rows have no intra-SM reuse, keep L1 for indices.
    int j = start;
    for (; j + 3 < end; j += 4) {
        const int   c0 = __ldg(token_code + j);
        const int   c1 = __ldg(token_code + j + 1);
        const int   c2 = __ldg(token_code + j + 2);
        const int   c3 = __ldg(token_code + j + 3);
        const float v0 = __ldg(spm_vals + j);
        const float v1 = __ldg(spm_vals + j + 1);
        const float v2 = __ldg(spm_vals + j + 2);
        const float v3 = __ldg(spm_vals + j + 3);
        const float4 f0 = __ldcg(token_ft + (size_t)c0 * (D / 4) + lane);
        const float4 f1 = __ldcg(token_ft + (size_t)c1 * (D / 4) + lane);
        const float4 f2 = __ldcg(token_ft + (size_t)c2 * (D / 4) + lane);
        const float4 f3 = __ldcg(token_ft + (size_t)c3 * (D / 4) + lane);
        acc.x += v0 * f0.x + v1 * f1.x + v2 * f2.x + v3 * f3.x;
        acc.y += v0 * f0.y + v1 * f1.y + v2 * f2.y + v3 * f3.y;
        acc.z += v0 * f0.z + v1 * f1.z + v2 * f2.z + v3 * f3.z;
        acc.w += v0 * f0.w + v1 * f1.w + v2 * f2.w + v3 * f3.w;
    }
    // Dense 2-wide + 1 tails (no clamped duplicate gathers).
    if (j + 1 < end) {
        const int   c0 = __ldg(token_code + j);
        const int   c1 = __ldg(token_code + j + 1);
        const float v0 = __ldg(spm_vals + j);
        const float v1 = __ldg(spm_vals + j + 1);
        const float4 f0 = __ldcg(token_ft + (size_t)c0 * (D / 4) + lane);
        const float4 f1 = __ldcg(token_ft + (size_t)c1 * (D / 4) + lane);
        acc.x += v0 * f0.x + v1 * f1.x;
        acc.y += v0 * f0.y + v1 * f1.y;
        acc.z += v0 * f0.z + v1 * f1.z;
        acc.w += v0 * f0.w + v1 * f1.w;
        j += 2;
    }
    if (j < end) {
        const int   c0 = __ldg(token_code + j);
        const float v0 = __ldg(spm_vals + j);
        const float4 f0 = __ldcg(token_ft + (size_t)c0 * (D / 4) + lane);
        acc.x += v0 * f0.x;
        acc.y += v0 * f0.y;
        acc.z += v0 * f0.z;
        acc.w += v0 * f0.w;
    }

    // Streaming store: one coalesced 1KB store per mention row; empty segments
    // write zeros (poisoned output fully initialized).
    __stcs(out + (size_t)group * (D / 4) + lane, acc);
}

extern "C" void kernel_launch(void* const* d_in, const int* in_sizes, int n_in,
                              void* d_out, int out_size)
{
    const float* token_ft   = (const float*)d_in[0]; // [262144, 256] f32
    const int*   token_code = (const int*)  d_in[1]; // [524288] i32
    const int*   spm_rows   = (const int*)  d_in[2]; // [524288] i32 sorted
    const float* spm_vals   = (const float*)d_in[3]; // [524288] f32
    float*       out        = (float*)d_out;         // [65536, 256] f32

    const int nnz = in_sizes[1];

    const int pro_threads = 512;
    const int pro_work    = (nnz + 3) / 4;                       // 131072 threads
    build_rowptr_kernel<<<(pro_work + pro_threads - 1) / pro_threads, pro_threads>>>(
        (const int4*)spm_rows, nnz);

    const int threads = LANES * GROUPS_PER_BLOCK;                               // 512
    const int blocks  = N_MENTIONS / GROUPS_PER_BLOCK;                          // 8192

    mention_segsum_kernel<<<blocks, threads>>>(
        (const float4*)token_ft, token_code, spm_vals, (float4*)out);
}